// round 13
// baseline (speedup 1.0000x reference)
#include <cuda_runtime.h>
#include <stdint.h>

// MinusSpan: B=16, T=2048, D=1024 (H=512), N_SPANS=256
// out[b,s] = concat(fwd[j]-f_pre, bwd[i]-b_post, f_pre, b_post), zeroed if i==0&&j==0
//
// R13: DE-BATCHED loads. All prior variants front-batched 4-16 LDG.128
// (MLP_p1 high) -> per the B300 spread model this maximizes cross-CTA
// L1tex-queue contention (spr up to ~2x) at oe~14. Here loads are issued in
// dependent pairs with barriers between groups (MLP_p1 ~ 2), trading unneeded
// latency-hiding (reads are warm-L2 hits in steady state) for low spread.

static constexpr int Bc = 16;
static constexpr int Tc = 2048;
static constexpr int Dc = 1024;
static constexpr int NS = 256;
static constexpr int D4 = Dc / 4;           // 256 float4 per (b,t) row
static constexpr int H4 = Dc / 8;           // 128 float4 per half-row
static constexpr int NSPAN_TOT = Bc * NS;   // 4096 spans
static constexpr int NSP = 2;               // spans per CTA

__device__ __forceinline__ void sched_fence() {
    asm volatile("" ::: "memory");
}

__global__ __launch_bounds__(128)
void minus_span_kernel(const float* __restrict__ inp,
                       const unsigned int* __restrict__ idxw,  // raw 32-bit view of span_idxs
                       float* __restrict__ out)
{
    const int t    = threadIdx.x;           // 0..127 (one float4 per region)
    const int lane = t & 31;

    // ---- per-warp index-dtype detection (no extra kernel launch) ----
    // int64 buffer (values < 2048, little-endian): every odd 32-bit word is a
    // zero high half. int32 buffer: odd words are random j in [0,2048) —
    // P(all 64 samples zero) ~ 0. Both layouts have >= 8192 words.
    unsigned w0 = __ldg(&idxw[2 * lane + 1]);
    unsigned w1 = __ldg(&idxw[2 * (lane + 32) + 1]);
    const bool is64 = (__ballot_sync(0xffffffffu, (w0 | w1) != 0u) == 0u);

    const int span0 = blockIdx.x * NSP;
    const float4* __restrict__ f4 = reinterpret_cast<const float4*>(inp);
    float4* __restrict__ o4 = reinterpret_cast<float4*>(out);
    const float4 zero = make_float4(0.f, 0.f, 0.f, 0.f);

    #pragma unroll
    for (int s = 0; s < NSP; s++) {
        const int span = span0 + s;
        const int b    = span >> 8;         // span / NS

        // Index values fit in the low 32-bit word under both layouts.
        int i, j;
        if (is64) {
            i = (int)idxw[4 * span + 0];
            j = (int)idxw[4 * span + 2];
        } else {
            i = (int)idxw[2 * span + 0];
            j = (int)idxw[2 * span + 1];
        }

        const bool skip  = (i == 0) && (j == 0);
        const bool hpre  = !skip && (i >= 1);
        const bool hpost = !skip && (j + 1 < Tc);

        // Safety clamp: garbage indices become wrong values, never faults.
        int ic = min(max(i, 0), Tc - 1);
        int jc = min(max(j, 0), Tc - 1);
        int ip = (ic >= 1) ? ic - 1 : 0;
        int jn = (jc + 1 < Tc) ? jc + 1 : Tc - 1;

        const unsigned base = (unsigned)b * (Tc * D4);
        const unsigned ofe = base + (unsigned)jc * D4 + t;        // fwd[j]
        const unsigned obs = base + (unsigned)ic * D4 + H4 + t;   // bwd[i]
        const unsigned ofp = base + (unsigned)ip * D4 + t;        // fwd[i-1]
        const unsigned obp = base + (unsigned)jn * D4 + H4 + t;   // bwd[j+1]
        const unsigned oo  = (unsigned)span * (4 * H4) + t;

        // ---- group 1: forward pair -> out rows 0 and 2 ----
        float4 fe = skip ? zero : __ldg(&f4[ofe]);
        float4 fp = hpre ? __ldg(&f4[ofp]) : zero;
        float4 r0 = make_float4(fe.x - fp.x, fe.y - fp.y,
                                fe.z - fp.z, fe.w - fp.w);
        o4[oo]          = r0;    // f_end - f_pre
        o4[oo + 2 * H4] = fp;    // f_pre
        sched_fence();           // keep group 2's loads below group 1's stores

        // ---- group 2: backward pair -> out rows 1 and 3 ----
        float4 bs = skip  ? zero : __ldg(&f4[obs]);
        float4 bp = hpost ? __ldg(&f4[obp]) : zero;
        float4 r1 = make_float4(bs.x - bp.x, bs.y - bp.y,
                                bs.z - bp.z, bs.w - bp.w);
        o4[oo + H4]     = r1;    // b_start - b_post
        o4[oo + 3 * H4] = bp;    // b_post
        sched_fence();
    }
}

extern "C" void kernel_launch(void* const* d_in, const int* in_sizes, int n_in,
                              void* d_out, int out_size)
{
    // Select inputs by element count, immune to ordering:
    // input: B*T*D = 33,554,432 elements; span_idxs: 8,192.
    int big   = (in_sizes[0] >= in_sizes[1]) ? 0 : 1;
    int small = 1 - big;

    const float*        inp  = (const float*)d_in[big];
    const unsigned int* idxs = (const unsigned int*)d_in[small];
    float*              out  = (float*)d_out;

    minus_span_kernel<<<NSPAN_TOT / NSP, 128>>>(inp, idxs, out);
}

// round 14
// speedup vs baseline: 1.2422x; 1.2422x over previous
#include <cuda_runtime.h>
#include <stdint.h>

// MinusSpan: B=16, T=2048, D=1024 (H=512), N_SPANS=256
// out[b,s] = concat(fwd[j]-f_pre, bwd[i]-b_post, f_pre, b_post), zeroed if i==0&&j==0
// f_pre = fwd[i-1] if i>=1 else 0 ; b_post = bwd[j+1] if j+1<T else 0
//
// R14: R11 winner's per-thread shape (8 batched LDG.128 + 8 STG.128, batched
// front) but consolidated: 256 threads/CTA handling NSP=4 spans, grid 1024.
// Same warps/SM residency, half the CTA scheduling events / ragged-wave
// imbalance. Warm steady state is LTS+overhead bound; this trims overhead.

static constexpr int Bc = 16;
static constexpr int Tc = 2048;
static constexpr int Dc = 1024;
static constexpr int NS = 256;
static constexpr int D4 = Dc / 4;           // 256 float4 per (b,t) row
static constexpr int H4 = Dc / 8;           // 128 float4 per half-row
static constexpr int NSPAN_TOT = Bc * NS;   // 4096 spans
static constexpr int NSP = 4;               // spans per CTA
static constexpr int NTHR = 256;            // threads per CTA
static constexpr int SPT = 2;               // spans handled per thread (NSP spans / 2 halves)

__global__ __launch_bounds__(NTHR)
void minus_span_kernel(const float* __restrict__ inp,
                       const unsigned int* __restrict__ idxw,  // raw 32-bit view of span_idxs
                       float* __restrict__ out)
{
    const int t    = threadIdx.x;           // 0..255
    const int lane = t & 31;
    const int half = t >> 7;                // 0: spans 0-1, 1: spans 2-3
    const int tt   = t & 127;               // float4 index within a region

    // ---- per-warp index-dtype detection (no extra kernel launch) ----
    // int64 buffer (values < 2048, little-endian): every odd 32-bit word is a
    // zero high half. int32 buffer: odd words are random j in [0,2048) —
    // P(all 64 samples zero) ~ 0. Both layouts have >= 8192 words.
    unsigned w0 = __ldg(&idxw[2 * lane + 1]);
    unsigned w1 = __ldg(&idxw[2 * (lane + 32) + 1]);
    const bool is64 = (__ballot_sync(0xffffffffu, (w0 | w1) != 0u) == 0u);

    const int span0 = blockIdx.x * NSP + half * SPT;   // this thread's 2 spans
    const float4* __restrict__ f4 = reinterpret_cast<const float4*>(inp);
    float4* __restrict__ o4 = reinterpret_cast<float4*>(out);
    const float4 zero = make_float4(0.f, 0.f, 0.f, 0.f);

    // Per-span state: 32-bit element offsets (max offset 8.4M < 2^31)
    unsigned ofe[SPT], obs[SPT], ofp[SPT], obp[SPT], oout[SPT];
    bool skip[SPT], hpre[SPT], hpost[SPT];

    #pragma unroll
    for (int s = 0; s < SPT; s++) {
        const int span = span0 + s;
        const int b    = span >> 8;         // span / NS

        // Index values fit in the low 32-bit word under both layouts.
        int i, j;
        if (is64) {
            i = (int)idxw[4 * span + 0];
            j = (int)idxw[4 * span + 2];
        } else {
            i = (int)idxw[2 * span + 0];
            j = (int)idxw[2 * span + 1];
        }

        skip[s]  = (i == 0) && (j == 0);
        hpre[s]  = !skip[s] && (i >= 1);
        hpost[s] = !skip[s] && (j + 1 < Tc);

        // Safety clamp: garbage indices become wrong values, never faults.
        int ic = min(max(i, 0), Tc - 1);
        int jc = min(max(j, 0), Tc - 1);
        int ip = (ic >= 1) ? ic - 1 : 0;
        int jn = (jc + 1 < Tc) ? jc + 1 : Tc - 1;

        const unsigned base = (unsigned)b * (Tc * D4);
        ofe[s]  = base + (unsigned)jc * D4 + tt;        // fwd[j]
        obs[s]  = base + (unsigned)ic * D4 + H4 + tt;   // bwd[i]
        ofp[s]  = base + (unsigned)ip * D4 + tt;        // fwd[i-1]
        obp[s]  = base + (unsigned)jn * D4 + H4 + tt;   // bwd[j+1]
        oout[s] = (unsigned)span * (4 * H4) + tt;       // output row base + tt
    }

    // ---- batch all 8 independent LDG.128s before any compute/store ----
    float4 fe[SPT], bs[SPT], fp[SPT], bp[SPT];
    #pragma unroll
    for (int s = 0; s < SPT; s++) {
        fe[s] = skip[s]  ? zero : __ldg(&f4[ofe[s]]);
        bs[s] = skip[s]  ? zero : __ldg(&f4[obs[s]]);
        fp[s] = hpre[s]  ? __ldg(&f4[ofp[s]]) : zero;
        bp[s] = hpost[s] ? __ldg(&f4[obp[s]]) : zero;
    }

    // ---- compute + plain write-back stores ----
    #pragma unroll
    for (int s = 0; s < SPT; s++) {
        float4 r0 = make_float4(fe[s].x - fp[s].x, fe[s].y - fp[s].y,
                                fe[s].z - fp[s].z, fe[s].w - fp[s].w);
        float4 r1 = make_float4(bs[s].x - bp[s].x, bs[s].y - bp[s].y,
                                bs[s].z - bp[s].z, bs[s].w - bp[s].w);

        o4[oout[s]]          = r0;      // f_end - f_pre
        o4[oout[s] + H4]     = r1;      // b_start - b_post
        o4[oout[s] + 2 * H4] = fp[s];   // f_pre
        o4[oout[s] + 3 * H4] = bp[s];   // b_post
    }
}

extern "C" void kernel_launch(void* const* d_in, const int* in_sizes, int n_in,
                              void* d_out, int out_size)
{
    // Select inputs by element count, immune to ordering:
    // input: B*T*D = 33,554,432 elements; span_idxs: 8,192.
    int big   = (in_sizes[0] >= in_sizes[1]) ? 0 : 1;
    int small = 1 - big;

    const float*        inp  = (const float*)d_in[big];
    const unsigned int* idxs = (const unsigned int*)d_in[small];
    float*              out  = (float*)d_out;

    minus_span_kernel<<<NSPAN_TOT / NSP, NTHR>>>(inp, idxs, out);
}

// round 15
// speedup vs baseline: 1.2674x; 1.0203x over previous
#include <cuda_runtime.h>
#include <stdint.h>

// MinusSpan: B=16, T=2048, D=1024 (H=512), N_SPANS=256
// out[b,s] = concat(fwd[j]-f_pre, bwd[i]-b_post, f_pre, b_post), zeroed if i==0&&j==0
// f_pre = fwd[i-1] if i>=1 else 0 ; b_post = bwd[j+1] if j+1<T else 0
//
// R15 (final form): the thrice-confirmed 10.72us winner (NSP=2, 128 thr,
// batched LDG.128, plain write-back stores), with the dtype probe trimmed to
// 32 samples. All other axes measured flat or worse across R3-R14; kernel sits
// on the LTS-traffic + launch-overhead floor (~66MB/replay through L2, L1D
// flushed per launch => irreducible).

static constexpr int Bc = 16;
static constexpr int Tc = 2048;
static constexpr int Dc = 1024;
static constexpr int NS = 256;
static constexpr int D4 = Dc / 4;           // 256 float4 per (b,t) row
static constexpr int H4 = Dc / 8;           // 128 float4 per half-row
static constexpr int NSPAN_TOT = Bc * NS;   // 4096 spans
static constexpr int NSP = 2;               // spans per CTA (proven optimum)

__global__ __launch_bounds__(128)
void minus_span_kernel(const float* __restrict__ inp,
                       const unsigned int* __restrict__ idxw,  // raw 32-bit view of span_idxs
                       float* __restrict__ out)
{
    const int t    = threadIdx.x;           // 0..127 (one float4 per region)
    const int lane = t & 31;

    // ---- per-warp index-dtype detection (fused; 32 samples suffice) ----
    // int64 buffer (values < 2048, little-endian): every odd 32-bit word is a
    // zero high half. int32 buffer: odd words are random j in [0,2048) —
    // P(all 32 samples zero) = 2048^-32 ~ 0. Both layouts have >= 8192 words.
    unsigned w0 = __ldg(&idxw[2 * lane + 1]);
    const bool is64 = (__ballot_sync(0xffffffffu, w0 != 0u) == 0u);

    const int span0 = blockIdx.x * NSP;
    const float4* __restrict__ f4 = reinterpret_cast<const float4*>(inp);
    float4* __restrict__ o4 = reinterpret_cast<float4*>(out);
    const float4 zero = make_float4(0.f, 0.f, 0.f, 0.f);

    // Per-span state: 32-bit element offsets (max offset 8.4M < 2^31)
    unsigned ofe[NSP], obs[NSP], ofp[NSP], obp[NSP], oout[NSP];
    bool skip[NSP], hpre[NSP], hpost[NSP];

    #pragma unroll
    for (int s = 0; s < NSP; s++) {
        const int span = span0 + s;
        const int b    = span >> 8;         // span / NS

        // Index values fit in the low 32-bit word under both layouts.
        int i, j;
        if (is64) {
            i = (int)idxw[4 * span + 0];
            j = (int)idxw[4 * span + 2];
        } else {
            i = (int)idxw[2 * span + 0];
            j = (int)idxw[2 * span + 1];
        }

        skip[s]  = (i == 0) && (j == 0);
        hpre[s]  = !skip[s] && (i >= 1);
        hpost[s] = !skip[s] && (j + 1 < Tc);

        // Safety clamp: garbage indices become wrong values, never faults.
        int ic = min(max(i, 0), Tc - 1);
        int jc = min(max(j, 0), Tc - 1);
        int ip = (ic >= 1) ? ic - 1 : 0;
        int jn = (jc + 1 < Tc) ? jc + 1 : Tc - 1;

        const unsigned base = (unsigned)b * (Tc * D4);
        ofe[s]  = base + (unsigned)jc * D4 + t;        // fwd[j]
        obs[s]  = base + (unsigned)ic * D4 + H4 + t;   // bwd[i]
        ofp[s]  = base + (unsigned)ip * D4 + t;        // fwd[i-1]
        obp[s]  = base + (unsigned)jn * D4 + H4 + t;   // bwd[j+1]
        oout[s] = (unsigned)span * (4 * H4) + t;       // output row base + t
    }

    // ---- batch all 8 independent LDG.128s before any compute/store ----
    float4 fe[NSP], bs[NSP], fp[NSP], bp[NSP];
    #pragma unroll
    for (int s = 0; s < NSP; s++) {
        fe[s] = skip[s]  ? zero : __ldg(&f4[ofe[s]]);
        bs[s] = skip[s]  ? zero : __ldg(&f4[obs[s]]);
        fp[s] = hpre[s]  ? __ldg(&f4[ofp[s]]) : zero;
        bp[s] = hpost[s] ? __ldg(&f4[obp[s]]) : zero;
    }

    // ---- compute + plain write-back stores ----
    #pragma unroll
    for (int s = 0; s < NSP; s++) {
        float4 r0 = make_float4(fe[s].x - fp[s].x, fe[s].y - fp[s].y,
                                fe[s].z - fp[s].z, fe[s].w - fp[s].w);
        float4 r1 = make_float4(bs[s].x - bp[s].x, bs[s].y - bp[s].y,
                                bs[s].z - bp[s].z, bs[s].w - bp[s].w);

        o4[oout[s]]          = r0;      // f_end - f_pre
        o4[oout[s] + H4]     = r1;      // b_start - b_post
        o4[oout[s] + 2 * H4] = fp[s];   // f_pre
        o4[oout[s] + 3 * H4] = bp[s];   // b_post
    }
}

extern "C" void kernel_launch(void* const* d_in, const int* in_sizes, int n_in,
                              void* d_out, int out_size)
{
    // Select inputs by element count, immune to ordering:
    // input: B*T*D = 33,554,432 elements; span_idxs: 8,192.
    int big   = (in_sizes[0] >= in_sizes[1]) ? 0 : 1;
    int small = 1 - big;

    const float*        inp  = (const float*)d_in[big];
    const unsigned int* idxs = (const unsigned int*)d_in[small];
    float*              out  = (float*)d_out;

    minus_span_kernel<<<NSPAN_TOT / NSP, 128>>>(inp, idxs, out);
}

// round 16
// speedup vs baseline: 1.2711x; 1.0029x over previous
#include <cuda_runtime.h>
#include <stdint.h>

// MinusSpan: B=16, T=2048, D=1024 (H=512), N_SPANS=256
// out[b,s] = concat(fwd[j]-f_pre, bwd[i]-b_post, f_pre, b_post), zeroed if i==0&&j==0
// f_pre = fwd[i-1] if i>=1 else 0 ; b_post = bwd[j+1] if j+1<T else 0
//
// R16: Blackwell 256-bit memory ops (LDG.E.256 / STG.256). Same winner layout
// (grid 2048, 128 thr, 2 spans/CTA) but each thread moves 32B per region:
// threads 0-63 -> span 0, threads 64-127 -> span 1. Halves memory-instruction
// count and L1 wavefronts per warp at identical logical traffic.

static constexpr int Bc = 16;
static constexpr int Tc = 2048;
static constexpr int Dc = 1024;
static constexpr int NS = 256;
static constexpr int D8 = Dc / 8;           // 128 float8(32B) chunks per (b,t) row
static constexpr int H8 = Dc / 16;          // 64 chunks per half-row
static constexpr int NSPAN_TOT = Bc * NS;   // 4096 spans
static constexpr int NSP = 2;               // spans per CTA

struct alignas(32) F8 { float4 a, b; };

__device__ __forceinline__ F8 ldg256(const F8* p) {
    F8 v;
    asm volatile("ld.global.nc.v8.f32 {%0,%1,%2,%3,%4,%5,%6,%7}, [%8];"
                 : "=f"(v.a.x), "=f"(v.a.y), "=f"(v.a.z), "=f"(v.a.w),
                   "=f"(v.b.x), "=f"(v.b.y), "=f"(v.b.z), "=f"(v.b.w)
                 : "l"(p));
    return v;
}
__device__ __forceinline__ void stg256(F8* p, const F8& v) {
    asm volatile("st.global.v8.f32 [%0], {%1,%2,%3,%4,%5,%6,%7,%8};"
                 :: "l"(p),
                    "f"(v.a.x), "f"(v.a.y), "f"(v.a.z), "f"(v.a.w),
                    "f"(v.b.x), "f"(v.b.y), "f"(v.b.z), "f"(v.b.w)
                 : "memory");
}

__global__ __launch_bounds__(128)
void minus_span_kernel(const float* __restrict__ inp,
                       const unsigned int* __restrict__ idxw,  // raw 32-bit view of span_idxs
                       float* __restrict__ out)
{
    const int t    = threadIdx.x;           // 0..127
    const int lane = t & 31;
    const int s    = t >> 6;                // which of the CTA's 2 spans
    const int c    = t & 63;                // 32B chunk within a region

    // ---- per-warp index-dtype detection (fused; 32 samples suffice) ----
    // int64 buffer (values < 2048, LE): every odd 32-bit word is a zero high
    // half. int32: odd words are random j in [0,2048) -> P(all 32 zero) ~ 0.
    unsigned w0 = __ldg(&idxw[2 * lane + 1]);
    const bool is64 = (__ballot_sync(0xffffffffu, w0 != 0u) == 0u);

    const int span = blockIdx.x * NSP + s;
    const int b    = span >> 8;             // span / NS

    // Index values fit in the low 32-bit word under both layouts.
    int i, j;
    if (is64) {
        i = (int)idxw[4 * span + 0];
        j = (int)idxw[4 * span + 2];
    } else {
        i = (int)idxw[2 * span + 0];
        j = (int)idxw[2 * span + 1];
    }

    const bool skip  = (i == 0) && (j == 0);
    const bool hpre  = !skip && (i >= 1);
    const bool hpost = !skip && (j + 1 < Tc);

    // Safety clamp: garbage indices become wrong values, never faults.
    int ic = min(max(i, 0), Tc - 1);
    int jc = min(max(j, 0), Tc - 1);
    int ip = (ic >= 1) ? ic - 1 : 0;
    int jn = (jc + 1 < Tc) ? jc + 1 : Tc - 1;

    const F8* __restrict__ f8 = reinterpret_cast<const F8*>(inp);
    F8* __restrict__ o8 = reinterpret_cast<F8*>(out);

    const unsigned base = (unsigned)b * (Tc * D8);
    const unsigned ofe = base + (unsigned)jc * D8 + c;        // fwd[j]
    const unsigned obs = base + (unsigned)ic * D8 + H8 + c;   // bwd[i]
    const unsigned ofp = base + (unsigned)ip * D8 + c;        // fwd[i-1]
    const unsigned obp = base + (unsigned)jn * D8 + H8 + c;   // bwd[j+1]
    const unsigned oo  = (unsigned)span * (4 * H8) + c;       // out row base + c

    F8 zero;
    zero.a = make_float4(0.f, 0.f, 0.f, 0.f);
    zero.b = zero.a;

    // ---- batch the 4 independent LDG.256s ----
    F8 fe = skip  ? zero : ldg256(&f8[ofe]);
    F8 bs = skip  ? zero : ldg256(&f8[obs]);
    F8 fp = hpre  ? ldg256(&f8[ofp]) : zero;
    F8 bp = hpost ? ldg256(&f8[obp]) : zero;

    // ---- compute ----
    F8 r0, r1;
    r0.a = make_float4(fe.a.x - fp.a.x, fe.a.y - fp.a.y, fe.a.z - fp.a.z, fe.a.w - fp.a.w);
    r0.b = make_float4(fe.b.x - fp.b.x, fe.b.y - fp.b.y, fe.b.z - fp.b.z, fe.b.w - fp.b.w);
    r1.a = make_float4(bs.a.x - bp.a.x, bs.a.y - bp.a.y, bs.a.z - bp.a.z, bs.a.w - bp.a.w);
    r1.b = make_float4(bs.b.x - bp.b.x, bs.b.y - bp.b.y, bs.b.z - bp.b.z, bs.b.w - bp.b.w);

    // ---- 4 STG.256 stores ----
    stg256(&o8[oo],          r0);   // f_end - f_pre
    stg256(&o8[oo + H8],     r1);   // b_start - b_post
    stg256(&o8[oo + 2 * H8], fp);   // f_pre
    stg256(&o8[oo + 3 * H8], bp);   // b_post
}

extern "C" void kernel_launch(void* const* d_in, const int* in_sizes, int n_in,
                              void* d_out, int out_size)
{
    // Select inputs by element count, immune to ordering:
    // input: B*T*D = 33,554,432 elements; span_idxs: 8,192.
    int big   = (in_sizes[0] >= in_sizes[1]) ? 0 : 1;
    int small = 1 - big;

    const float*        inp  = (const float*)d_in[big];
    const unsigned int* idxs = (const unsigned int*)d_in[small];
    float*              out  = (float*)d_out;

    minus_span_kernel<<<NSPAN_TOT / NSP, 128>>>(inp, idxs, out);
}

// round 17
// speedup vs baseline: 1.2749x; 1.0029x over previous
#include <cuda_runtime.h>
#include <stdint.h>

// MinusSpan: B=16, T=2048, D=1024 (H=512), N_SPANS=256
// out[b,s] = concat(fwd[j]-f_pre, bwd[i]-b_post, f_pre, b_post), zeroed if i==0&&j==0
// f_pre = fwd[i-1] if i>=1 else 0 ; b_post = bwd[j+1] if j+1<T else 0
//
// FINAL (R17): exact re-land of the R11 configuration, which measured
// 10.72us on three independent runs — the best of 14 measured variants.
// Convergence evidence: load machinery (MLP/prefetch/DMA), store policy
// (wb/.cs/.wt), issue rate (128b vs 256b ops), batching order, and CTA
// shape all measured flat or worse. Kernel sits on the irreducible
// LTS-traffic (~66MB/replay) + launch-overhead floor.

static constexpr int Bc = 16;
static constexpr int Tc = 2048;
static constexpr int Dc = 1024;
static constexpr int NS = 256;
static constexpr int D4 = Dc / 4;           // 256 float4 per (b,t) row
static constexpr int H4 = Dc / 8;           // 128 float4 per half-row
static constexpr int NSPAN_TOT = Bc * NS;   // 4096 spans
static constexpr int NSP = 2;               // spans per CTA (proven optimum)

__global__ __launch_bounds__(128)
void minus_span_kernel(const float* __restrict__ inp,
                       const unsigned int* __restrict__ idxw,  // raw 32-bit view of span_idxs
                       float* __restrict__ out)
{
    const int t    = threadIdx.x;           // 0..127 (one float4 per region)
    const int lane = t & 31;

    // ---- per-warp index-dtype detection (no extra kernel launch) ----
    // int64 buffer (values < 2048, little-endian): every odd 32-bit word is a
    // zero high half. int32 buffer: odd words are random j in [0,2048) —
    // P(all 64 samples zero) ~ 0. Both layouts have >= 8192 words.
    unsigned w0 = __ldg(&idxw[2 * lane + 1]);
    unsigned w1 = __ldg(&idxw[2 * (lane + 32) + 1]);
    const bool is64 = (__ballot_sync(0xffffffffu, (w0 | w1) != 0u) == 0u);

    const int span0 = blockIdx.x * NSP;
    const float4* __restrict__ f4 = reinterpret_cast<const float4*>(inp);
    float4* __restrict__ o4 = reinterpret_cast<float4*>(out);
    const float4 zero = make_float4(0.f, 0.f, 0.f, 0.f);

    // Per-span state: 32-bit element offsets (max offset 8.4M < 2^31)
    unsigned ofe[NSP], obs[NSP], ofp[NSP], obp[NSP], oout[NSP];
    bool skip[NSP], hpre[NSP], hpost[NSP];

    #pragma unroll
    for (int s = 0; s < NSP; s++) {
        const int span = span0 + s;
        const int b    = span >> 8;         // span / NS

        // Index values fit in the low 32-bit word under both layouts.
        int i, j;
        if (is64) {
            i = (int)idxw[4 * span + 0];
            j = (int)idxw[4 * span + 2];
        } else {
            i = (int)idxw[2 * span + 0];
            j = (int)idxw[2 * span + 1];
        }

        skip[s]  = (i == 0) && (j == 0);
        hpre[s]  = !skip[s] && (i >= 1);
        hpost[s] = !skip[s] && (j + 1 < Tc);

        // Safety clamp: garbage indices become wrong values, never faults.
        int ic = min(max(i, 0), Tc - 1);
        int jc = min(max(j, 0), Tc - 1);
        int ip = (ic >= 1) ? ic - 1 : 0;
        int jn = (jc + 1 < Tc) ? jc + 1 : Tc - 1;

        const unsigned base = (unsigned)b * (Tc * D4);
        ofe[s]  = base + (unsigned)jc * D4 + t;        // fwd[j]
        obs[s]  = base + (unsigned)ic * D4 + H4 + t;   // bwd[i]
        ofp[s]  = base + (unsigned)ip * D4 + t;        // fwd[i-1]
        obp[s]  = base + (unsigned)jn * D4 + H4 + t;   // bwd[j+1]
        oout[s] = (unsigned)span * (4 * H4) + t;       // output row base + t
    }

    // ---- batch all 8 independent LDG.128s before any compute/store ----
    float4 fe[NSP], bs[NSP], fp[NSP], bp[NSP];
    #pragma unroll
    for (int s = 0; s < NSP; s++) {
        fe[s] = skip[s]  ? zero : __ldg(&f4[ofe[s]]);
        bs[s] = skip[s]  ? zero : __ldg(&f4[obs[s]]);
        fp[s] = hpre[s]  ? __ldg(&f4[ofp[s]]) : zero;
        bp[s] = hpost[s] ? __ldg(&f4[obp[s]]) : zero;
    }

    // ---- compute + plain write-back stores ----
    #pragma unroll
    for (int s = 0; s < NSP; s++) {
        float4 r0 = make_float4(fe[s].x - fp[s].x, fe[s].y - fp[s].y,
                                fe[s].z - fp[s].z, fe[s].w - fp[s].w);
        float4 r1 = make_float4(bs[s].x - bp[s].x, bs[s].y - bp[s].y,
                                bs[s].z - bp[s].z, bs[s].w - bp[s].w);

        o4[oout[s]]          = r0;      // f_end - f_pre
        o4[oout[s] + H4]     = r1;      // b_start - b_post
        o4[oout[s] + 2 * H4] = fp[s];   // f_pre
        o4[oout[s] + 3 * H4] = bp[s];   // b_post
    }
}

extern "C" void kernel_launch(void* const* d_in, const int* in_sizes, int n_in,
                              void* d_out, int out_size)
{
    // Select inputs by element count, immune to ordering:
    // input: B*T*D = 33,554,432 elements; span_idxs: 8,192.
    int big   = (in_sizes[0] >= in_sizes[1]) ? 0 : 1;
    int small = 1 - big;

    const float*        inp  = (const float*)d_in[big];
    const unsigned int* idxs = (const unsigned int*)d_in[small];
    float*              out  = (float*)d_out;

    minus_span_kernel<<<NSPAN_TOT / NSP, 128>>>(inp, idxs, out);
}